// round 14
// baseline (speedup 1.0000x reference)
#include <cuda_runtime.h>
#include <math.h>

#define N_NODES 50000
#define N_PAIRS 4096
#define N_EDGESC 500000
#define N_SP    1000000
#define FEAT 300
#define HID 128
#define HEADS 3
#define H1DIM 384
#define OUTC 10
#define ETOT (N_EDGESC + N_NODES)
#define KSPLIT 4

// ------------------- scratch (device globals; no allocation) -------------------
__device__ float g_q[N_PAIRS * FEAT];
__device__ float g_k[N_PAIRS * FEAT];
__device__ float g_v[N_PAIRS * FEAT];
__device__ float g_S[(size_t)N_PAIRS * N_PAIRS];
__device__ float g_part[(size_t)KSPLIT * N_PAIRS * FEAT];
__device__ float g_attn[N_PAIRS * FEAT];
__device__ float g_fused[N_PAIRS * FEAT];
__device__ float g_xw[(size_t)N_NODES * FEAT];
__device__ float g_h1[(size_t)N_NODES * H1DIM];
__device__ float g_out1[(size_t)N_NODES * H1DIM];
__device__ float g_h2[N_NODES * OUTC];
__device__ float g_emb[N_NODES * OUTC];
__device__ float g_es1[N_NODES * HEADS];
__device__ float g_ed1[N_NODES * HEADS];
__device__ float g_es2[N_NODES];
__device__ float g_ed2[N_NODES];
__device__ int   g_deg[N_NODES];
__device__ int   g_rowptr[N_NODES + 1];
__device__ int   g_cursor[N_NODES];
__device__ int   g_adj[ETOT];
__device__ int   g_winner[N_NODES];

__device__ __forceinline__ float lrelu(float x) { return x > 0.f ? x : 0.2f * x; }

// ------------------- SGEMM core: 128x64 tile, 8x4 microtile, BK=16 -----------
// 1.5B LDS per FMA (vs 2.0 for 4x4) -> less crossbar pressure, ~60 regs.
// A: [M,K] row-major. TB=false: B [K,N]. TB=true: B [N,K] (C = A @ B^T).
template <bool TB>
__device__ __forceinline__ void gemm_body(
    const float* __restrict__ A, const float* __restrict__ B,
    const float* __restrict__ bias, const float* __restrict__ addm,
    float* __restrict__ C, int M, int N, int K, int kbeg, int kend)
{
    __shared__ __align__(16) float As[16][132];
    __shared__ __align__(16) float Bs[16][68];
    int bm = blockIdx.y * 128, bn = blockIdx.x * 64;
    int tid = threadIdx.x;
    int tx = tid & 15, ty = tid >> 4;
    float acc[8][4] = {};

    for (int k0 = kbeg; k0 < kend; k0 += 16) {
        // ---- A tile: 128 rows x 16 k (8 elems/thread, coalesced in k) ----
#pragma unroll
        for (int i = 0; i < 8; i++) {
            int idx = tid + 256 * i;
            int m = idx >> 4, kk = idx & 15;
            int gm = bm + m, gk = k0 + kk;
            As[kk][m] = (gm < M && gk < kend) ? A[(size_t)gm * K + gk] : 0.f;
        }
        // ---- B tile: 64 cols x 16 k (4 elems/thread) ----
        if (!TB) {
#pragma unroll
            for (int i = 0; i < 4; i++) {
                int idx = tid + 256 * i;
                int kk = idx >> 6, nn = idx & 63;
                int gk = k0 + kk, gn = bn + nn;
                Bs[kk][nn] = (gk < kend && gn < N) ? B[(size_t)gk * N + gn] : 0.f;
            }
        } else {
#pragma unroll
            for (int i = 0; i < 4; i++) {
                int idx = tid + 256 * i;
                int nn = idx >> 4, kk = idx & 15;
                int gn = bn + nn, gk = k0 + kk;
                Bs[kk][nn] = (gn < N && gk < kend) ? B[(size_t)gn * K + gk] : 0.f;
            }
        }
        __syncthreads();
#pragma unroll
        for (int kk = 0; kk < 16; kk++) {
            float4 a0 = *reinterpret_cast<const float4*>(&As[kk][ty * 8]);
            float4 a1 = *reinterpret_cast<const float4*>(&As[kk][ty * 8 + 4]);
            float4 bv = *reinterpret_cast<const float4*>(&Bs[kk][tx * 4]);
            float a[8] = {a0.x, a0.y, a0.z, a0.w, a1.x, a1.y, a1.z, a1.w};
            float b[4] = {bv.x, bv.y, bv.z, bv.w};
#pragma unroll
            for (int i = 0; i < 8; i++)
#pragma unroll
                for (int j = 0; j < 4; j++)
                    acc[i][j] += a[i] * b[j];
        }
        __syncthreads();
    }
#pragma unroll
    for (int i = 0; i < 8; i++) {
        int gm = bm + ty * 8 + i;
        if (gm >= M) continue;
#pragma unroll
        for (int j = 0; j < 4; j++) {
            int gn = bn + tx * 4 + j;
            if (gn >= N) continue;
            float vv = acc[i][j];
            if (bias) vv += bias[gn];
            if (addm) vv += addm[(size_t)gm * N + gn];
            C[(size_t)gm * N + gn] = vv;
        }
    }
}

template <bool TB>
__global__ void sgemm_kernel(const float* __restrict__ A, const float* __restrict__ B,
                             const float* __restrict__ bias, const float* __restrict__ addm,
                             float* __restrict__ C, int M, int N, int K)
{
    gemm_body<TB>(A, B, bias, addm, C, M, N, K, 0, K);
}

// split-K: grid.z slices of K, partials into Cpart[z][M*N]
__global__ void sgemm_splitk_kernel(const float* __restrict__ A, const float* __restrict__ B,
                                    float* __restrict__ Cpart, int M, int N, int K, int klen)
{
    int kbeg = blockIdx.z * klen;
    int kend = kbeg + klen < K ? kbeg + klen : K;
    gemm_body<false>(A, B, nullptr, nullptr,
                     Cpart + (size_t)blockIdx.z * M * N, M, N, K, kbeg, kend);
}

__global__ void splitk_reduce_kernel(const float4* __restrict__ part,
                                     const float4* __restrict__ addm,
                                     float4* __restrict__ C, int n4, size_t stride4)
{
    int i = blockIdx.x * blockDim.x + threadIdx.x;
    if (i >= n4) return;
    float4 s = addm[i];
#pragma unroll
    for (int z = 0; z < KSPLIT; z++) {
        float4 p = part[(size_t)z * stride4 + i];
        s.x += p.x; s.y += p.y; s.z += p.z; s.w += p.w;
    }
    C[i] = s;
}

// batched q/k/v projection: grid.z picks (A,B,bias,C)
__global__ void qkv_kernel(const float* __restrict__ fs, const float* __restrict__ fc,
                           const float* __restrict__ Wq, const float* __restrict__ bq,
                           const float* __restrict__ Wk, const float* __restrict__ bk,
                           const float* __restrict__ Wv, const float* __restrict__ bv,
                           float* __restrict__ q, float* __restrict__ k, float* __restrict__ v)
{
    const float* A; const float* B; const float* bias; float* C;
    if (blockIdx.z == 0)      { A = fs; B = Wq; bias = bq; C = q; }
    else if (blockIdx.z == 1) { A = fc; B = Wk; bias = bk; C = k; }
    else                      { A = fc; B = Wv; bias = bv; C = v; }
    gemm_body<false>(A, B, bias, nullptr, C, N_PAIRS, FEAT, FEAT, 0, FEAT);
}

// ------------------- row softmax of the 4096x4096 score matrix ---------------
__global__ void softmax4096(float* __restrict__ S)
{
    int row = blockIdx.x;
    float4* r = reinterpret_cast<float4*>(S + (size_t)row * 4096);
    const float scale = 0.05773502691896258f; // 1/sqrt(300)
    float4 vals[4];
    float mx = -1e30f;
#pragma unroll
    for (int i = 0; i < 4; i++) {
        float4 v = r[threadIdx.x + 256 * i];
        v.x *= scale; v.y *= scale; v.z *= scale; v.w *= scale;
        vals[i] = v;
        mx = fmaxf(mx, fmaxf(fmaxf(v.x, v.y), fmaxf(v.z, v.w)));
    }
    __shared__ float sh[8];
    for (int o = 16; o; o >>= 1) mx = fmaxf(mx, __shfl_xor_sync(0xffffffffu, mx, o));
    int w = threadIdx.x >> 5;
    if ((threadIdx.x & 31) == 0) sh[w] = mx;
    __syncthreads();
    mx = sh[0];
#pragma unroll
    for (int i = 1; i < 8; i++) mx = fmaxf(mx, sh[i]);
    __syncthreads();
    float se = 0.f;
#pragma unroll
    for (int i = 0; i < 4; i++) {
        vals[i].x = __expf(vals[i].x - mx); vals[i].y = __expf(vals[i].y - mx);
        vals[i].z = __expf(vals[i].z - mx); vals[i].w = __expf(vals[i].w - mx);
        se += vals[i].x + vals[i].y + vals[i].z + vals[i].w;
    }
    for (int o = 16; o; o >>= 1) se += __shfl_xor_sync(0xffffffffu, se, o);
    if ((threadIdx.x & 31) == 0) sh[w] = se;
    __syncthreads();
    se = 0.f;
#pragma unroll
    for (int i = 0; i < 8; i++) se += sh[i];
    float inv = 1.f / se;
#pragma unroll
    for (int i = 0; i < 4; i++) {
        vals[i].x *= inv; vals[i].y *= inv; vals[i].z *= inv; vals[i].w *= inv;
        r[threadIdx.x + 256 * i] = vals[i];
    }
}

// ------------------- x_work = x; scatter fused rows (last-index-wins) --------
__global__ void copy_x_kernel(const float4* __restrict__ x)
{
    size_t t = (size_t)blockIdx.x * blockDim.x + threadIdx.x;
    if (t < (size_t)N_NODES * FEAT / 4) reinterpret_cast<float4*>(g_xw)[t] = x[t];
}

__global__ void winner_init_kernel()
{
    int n = blockIdx.x * blockDim.x + threadIdx.x;
    if (n < N_NODES) g_winner[n] = -1;
}

__global__ void winner_max_kernel(const int* __restrict__ cidx)
{
    int i = blockIdx.x * blockDim.x + threadIdx.x;
    if (i < N_PAIRS) atomicMax(&g_winner[cidx[i]], i);
}

__global__ void scatter_fused_kernel(const int* __restrict__ cidx)
{
    int t = blockIdx.x * blockDim.x + threadIdx.x;
    if (t < N_PAIRS * FEAT) {
        int i = t / FEAT, c = t - i * FEAT;
        int node = cidx[i];
        if (g_winner[node] == i) g_xw[(size_t)node * FEAT + c] = g_fused[t];
    }
}

// ------------------- CSR build (by dst, includes self-loops) -----------------
__global__ void deg_init_kernel()
{
    int n = blockIdx.x * blockDim.x + threadIdx.x;
    if (n < N_NODES) g_deg[n] = 1;  // self-loop
}

__global__ void deg_count_kernel(const int* __restrict__ dst)
{
    int e = blockIdx.x * blockDim.x + threadIdx.x;
    if (e < N_EDGESC) atomicAdd(&g_deg[dst[e]], 1);
}

__global__ void exscan_kernel()
{
    __shared__ int wsum[32];
    __shared__ int carry;
    if (threadIdx.x == 0) carry = 0;
    int lane = threadIdx.x & 31, wid = threadIdx.x >> 5;
    __syncthreads();
    for (int base = 0; base < N_NODES; base += 1024) {
        int i = base + threadIdx.x;
        int v = (i < N_NODES) ? g_deg[i] : 0;
        int x = v;
        for (int o = 1; o < 32; o <<= 1) {
            int t = __shfl_up_sync(0xffffffffu, x, o);
            if (lane >= o) x += t;
        }
        if (lane == 31) wsum[wid] = x;
        __syncthreads();
        if (wid == 0) {
            int y = wsum[lane];
            for (int o = 1; o < 32; o <<= 1) {
                int t = __shfl_up_sync(0xffffffffu, y, o);
                if (lane >= o) y += t;
            }
            wsum[lane] = y;
        }
        __syncthreads();
        int incl = x + (wid ? wsum[wid - 1] : 0);
        int c = carry;
        if (i < N_NODES) g_rowptr[i + 1] = c + incl;
        __syncthreads();
        if (threadIdx.x == 1023) carry = c + incl;
        __syncthreads();
    }
    if (threadIdx.x == 0) g_rowptr[0] = 0;
}

__global__ void cursor_copy_kernel()
{
    int n = blockIdx.x * blockDim.x + threadIdx.x;
    if (n < N_NODES) g_cursor[n] = g_rowptr[n];
}

__global__ void fill_edges_kernel(const int* __restrict__ src, const int* __restrict__ dst)
{
    int e = blockIdx.x * blockDim.x + threadIdx.x;
    if (e < N_EDGESC) {
        int d = dst[e];
        int p = atomicAdd(&g_cursor[d], 1);
        g_adj[p] = src[e];
    }
}

__global__ void fill_self_kernel()
{
    int n = blockIdx.x * blockDim.x + threadIdx.x;
    if (n < N_NODES) {
        int p = atomicAdd(&g_cursor[n], 1);
        g_adj[p] = n;
    }
}

// ------------------- layer-1 attention coefficients (warp per node-head) -----
__global__ void e1_kernel(const float* __restrict__ asrc, const float* __restrict__ adst)
{
    int g = blockIdx.x * (blockDim.x >> 5) + (threadIdx.x >> 5);
    if (g >= N_NODES * HEADS) return;
    int n = g / 3, h = g - n * 3;
    int lane = threadIdx.x & 31;
    const float4* row = reinterpret_cast<const float4*>(g_h1 + (size_t)n * H1DIM + h * HID);
    const float4* as4 = reinterpret_cast<const float4*>(asrc + h * HID);
    const float4* ad4 = reinterpret_cast<const float4*>(adst + h * HID);
    float4 hv = row[lane], av = as4[lane], dv = ad4[lane];
    float s = hv.x * av.x + hv.y * av.y + hv.z * av.z + hv.w * av.w;
    float d = hv.x * dv.x + hv.y * dv.y + hv.z * dv.z + hv.w * dv.w;
    for (int o = 16; o; o >>= 1) {
        s += __shfl_xor_sync(0xffffffffu, s, o);
        d += __shfl_xor_sync(0xffffffffu, d, o);
    }
    if (lane == 0) {
        g_es1[n * HEADS + h] = s;
        g_ed1[n * HEADS + h] = d;
    }
}

// ------------------- GAT layer-1 aggregation (warp per node) + bias + ELU ----
__global__ void gat_agg1_kernel(const float* __restrict__ b1)
{
    int n = blockIdx.x * (blockDim.x >> 5) + (threadIdx.x >> 5);
    int lane = threadIdx.x & 31;
    if (n >= N_NODES) return;
    int s = g_rowptr[n], e = g_rowptr[n + 1];
    float ed0 = g_ed1[n * 3 + 0], ed1 = g_ed1[n * 3 + 1], ed2 = g_ed1[n * 3 + 2];

    float m0 = -1e30f, m1 = -1e30f, m2 = -1e30f;
    for (int j = s + lane; j < e; j += 32) {
        int sj = g_adj[j];
        m0 = fmaxf(m0, lrelu(g_es1[sj * 3 + 0] + ed0));
        m1 = fmaxf(m1, lrelu(g_es1[sj * 3 + 1] + ed1));
        m2 = fmaxf(m2, lrelu(g_es1[sj * 3 + 2] + ed2));
    }
    for (int o = 16; o; o >>= 1) {
        m0 = fmaxf(m0, __shfl_xor_sync(0xffffffffu, m0, o));
        m1 = fmaxf(m1, __shfl_xor_sync(0xffffffffu, m1, o));
        m2 = fmaxf(m2, __shfl_xor_sync(0xffffffffu, m2, o));
    }
    float d0 = 0.f, d1 = 0.f, d2 = 0.f;
    for (int j = s + lane; j < e; j += 32) {
        int sj = g_adj[j];
        d0 += __expf(lrelu(g_es1[sj * 3 + 0] + ed0) - m0);
        d1 += __expf(lrelu(g_es1[sj * 3 + 1] + ed1) - m1);
        d2 += __expf(lrelu(g_es1[sj * 3 + 2] + ed2) - m2);
    }
    for (int o = 16; o; o >>= 1) {
        d0 += __shfl_xor_sync(0xffffffffu, d0, o);
        d1 += __shfl_xor_sync(0xffffffffu, d1, o);
        d2 += __shfl_xor_sync(0xffffffffu, d2, o);
    }
    float inv0 = 1.f / (d0 + 1e-16f), inv1 = 1.f / (d1 + 1e-16f), inv2 = 1.f / (d2 + 1e-16f);

    // chunked accumulation: each lane computes alpha for ONE edge, broadcast
    float4 acc0 = {0, 0, 0, 0}, acc1 = {0, 0, 0, 0}, acc2 = {0, 0, 0, 0};
    for (int base = s; base < e; base += 32) {
        int j = base + lane;
        int sj = 0;
        float w0 = 0.f, w1 = 0.f, w2 = 0.f;
        if (j < e) {
            sj = g_adj[j];
            w0 = __expf(lrelu(g_es1[sj * 3 + 0] + ed0) - m0) * inv0;
            w1 = __expf(lrelu(g_es1[sj * 3 + 1] + ed1) - m1) * inv1;
            w2 = __expf(lrelu(g_es1[sj * 3 + 2] + ed2) - m2) * inv2;
        }
        int cnt = e - base; if (cnt > 32) cnt = 32;
        for (int t = 0; t < cnt; t++) {
            int   sjt = __shfl_sync(0xffffffffu, sj, t);
            float u0  = __shfl_sync(0xffffffffu, w0, t);
            float u1  = __shfl_sync(0xffffffffu, w1, t);
            float u2  = __shfl_sync(0xffffffffu, w2, t);
            const float4* row = reinterpret_cast<const float4*>(g_h1 + (size_t)sjt * H1DIM);
            float4 r0 = row[lane], r1 = row[lane + 32], r2 = row[lane + 64];
            acc0.x += u0 * r0.x; acc0.y += u0 * r0.y; acc0.z += u0 * r0.z; acc0.w += u0 * r0.w;
            acc1.x += u1 * r1.x; acc1.y += u1 * r1.y; acc1.z += u1 * r1.z; acc1.w += u1 * r1.w;
            acc2.x += u2 * r2.x; acc2.y += u2 * r2.y; acc2.z += u2 * r2.z; acc2.w += u2 * r2.w;
        }
    }
    // bias + ELU, vectorized store
    float* o = g_out1 + (size_t)n * H1DIM;
    const float4* bv = reinterpret_cast<const float4*>(b1);
    float4 outv;
    float4 bb = bv[lane];
    outv.x = acc0.x + bb.x; outv.y = acc0.y + bb.y; outv.z = acc0.z + bb.z; outv.w = acc0.w + bb.w;
    outv.x = outv.x > 0.f ? outv.x : expm1f(outv.x);
    outv.y = outv.y > 0.f ? outv.y : expm1f(outv.y);
    outv.z = outv.z > 0.f ? outv.z : expm1f(outv.z);
    outv.w = outv.w > 0.f ? outv.w : expm1f(outv.w);
    reinterpret_cast<float4*>(o)[lane] = outv;
    bb = bv[lane + 32];
    outv.x = acc1.x + bb.x; outv.y = acc1.y + bb.y; outv.z = acc1.z + bb.z; outv.w = acc1.w + bb.w;
    outv.x = outv.x > 0.f ? outv.x : expm1f(outv.x);
    outv.y = outv.y > 0.f ? outv.y : expm1f(outv.y);
    outv.z = outv.z > 0.f ? outv.z : expm1f(outv.z);
    outv.w = outv.w > 0.f ? outv.w : expm1f(outv.w);
    reinterpret_cast<float4*>(o)[lane + 32] = outv;
    bb = bv[lane + 64];
    outv.x = acc2.x + bb.x; outv.y = acc2.y + bb.y; outv.z = acc2.z + bb.z; outv.w = acc2.w + bb.w;
    outv.x = outv.x > 0.f ? outv.x : expm1f(outv.x);
    outv.y = outv.y > 0.f ? outv.y : expm1f(outv.y);
    outv.z = outv.z > 0.f ? outv.z : expm1f(outv.z);
    outv.w = outv.w > 0.f ? outv.w : expm1f(outv.w);
    reinterpret_cast<float4*>(o)[lane + 64] = outv;
}

// ------------------- h2 = out1 @ W2 (N=10) + e2 coefficients, warp per row ---
__global__ void w2e2_kernel(const float* __restrict__ W2,
                            const float* __restrict__ as2, const float* __restrict__ ad2)
{
    __shared__ float wT[OUTC * H1DIM];  // transposed: wT[c*384+k]
    for (int idx = threadIdx.x; idx < H1DIM * OUTC; idx += blockDim.x) {
        int k = idx / OUTC, c = idx - k * OUTC;
        wT[c * H1DIM + k] = W2[idx];
    }
    __syncthreads();
    int warp = threadIdx.x >> 5, lane = threadIdx.x & 31;
    int row = blockIdx.x * 8 + warp;
    if (row >= N_NODES) return;
    float acc[OUTC] = {};
    const float* xr = g_out1 + (size_t)row * H1DIM;
    for (int k = lane; k < H1DIM; k += 32) {
        float xv = xr[k];
#pragma unroll
        for (int c = 0; c < OUTC; c++) acc[c] += xv * wT[c * H1DIM + k];
    }
#pragma unroll
    for (int c = 0; c < OUTC; c++)
        for (int o = 16; o; o >>= 1) acc[c] += __shfl_xor_sync(0xffffffffu, acc[c], o);
    if (lane == 0) {
        float s = 0.f, d = 0.f;
#pragma unroll
        for (int c = 0; c < OUTC; c++) {
            g_h2[(size_t)row * OUTC + c] = acc[c];  // no bias before attention
            s += acc[c] * as2[c];
            d += acc[c] * ad2[c];
        }
        g_es2[row] = s;
        g_ed2[row] = d;
    }
}

// ------------------- GAT layer-2 aggregation (warp per node) + bias ----------
__global__ void gat_agg2_kernel(const float* __restrict__ b2)
{
    int n = blockIdx.x * (blockDim.x >> 5) + (threadIdx.x >> 5);
    int lane = threadIdx.x & 31;
    if (n >= N_NODES) return;
    int s = g_rowptr[n], e = g_rowptr[n + 1];
    float ed = g_ed2[n];

    float m = -1e30f;
    for (int j = s + lane; j < e; j += 32) m = fmaxf(m, lrelu(g_es2[g_adj[j]] + ed));
    for (int o = 16; o; o >>= 1) m = fmaxf(m, __shfl_xor_sync(0xffffffffu, m, o));
    float den = 0.f;
    for (int j = s + lane; j < e; j += 32) den += __expf(lrelu(g_es2[g_adj[j]] + ed) - m);
    for (int o = 16; o; o >>= 1) den += __shfl_xor_sync(0xffffffffu, den, o);
    float inv = 1.f / (den + 1e-16f);

    float acc[OUTC] = {};
    for (int j = s + lane; j < e; j += 32) {
        int sj = g_adj[j];
        float al = __expf(lrelu(g_es2[sj] + ed) - m) * inv;
        const float* r = g_h2 + (size_t)sj * OUTC;
#pragma unroll
        for (int c = 0; c < OUTC; c++) acc[c] += al * r[c];
    }
#pragma unroll
    for (int c = 0; c < OUTC; c++)
        for (int o = 16; o; o >>= 1) acc[c] += __shfl_xor_sync(0xffffffffu, acc[c], o);
    if (lane == 0) {
#pragma unroll
        for (int c = 0; c < OUTC; c++) g_emb[(size_t)n * OUTC + c] = acc[c] + b2[c];
    }
}

// ------------------- pair scoring --------------------------------------------
__global__ void score_kernel(const int* __restrict__ pair, float* __restrict__ out)
{
    int p = blockIdx.x * blockDim.x + threadIdx.x;
    if (p >= N_SP) return;
    const float* a = g_emb + (size_t)pair[2 * p] * OUTC;
    const float* b = g_emb + (size_t)pair[2 * p + 1] * OUTC;
    float s = 0.f;
#pragma unroll
    for (int c = 0; c < OUTC; c++) s += a[c] * b[c];
    out[p] = s;
}

// ------------------- host orchestration --------------------------------------
extern "C" void kernel_launch(void* const* d_in, const int* in_sizes, int n_in,
                              void* d_out, int out_size)
{
    const float* f_sub  = (const float*)d_in[0];
    const float* f_com  = (const float*)d_in[1];
    const float* x      = (const float*)d_in[2];
    const int*   com_ix = (const int*)d_in[3];
    const int*   eidx   = (const int*)d_in[4];
    const int*   pair   = (const int*)d_in[5];
    const float* Wq = (const float*)d_in[6],  *bq = (const float*)d_in[7];
    const float* Wk = (const float*)d_in[8],  *bk = (const float*)d_in[9];
    const float* Wv = (const float*)d_in[10], *bv = (const float*)d_in[11];
    const float* Wf = (const float*)d_in[12], *bf = (const float*)d_in[13];
    const float* W1 = (const float*)d_in[14];
    const float* as1 = (const float*)d_in[15], *ad1 = (const float*)d_in[16];
    const float* b1 = (const float*)d_in[17];
    const float* W2 = (const float*)d_in[18];
    const float* as2 = (const float*)d_in[19], *ad2 = (const float*)d_in[20];
    const float* b2 = (const float*)d_in[21];
    float* out = (float*)d_out;

    const int* src = eidx;
    const int* dst = eidx + N_EDGESC;

    float *qp, *kp, *vp, *Sp, *partp, *attnp, *fusedp, *xwp, *h1p;
    cudaGetSymbolAddress((void**)&qp, g_q);
    cudaGetSymbolAddress((void**)&kp, g_k);
    cudaGetSymbolAddress((void**)&vp, g_v);
    cudaGetSymbolAddress((void**)&Sp, g_S);
    cudaGetSymbolAddress((void**)&partp, g_part);
    cudaGetSymbolAddress((void**)&attnp, g_attn);
    cudaGetSymbolAddress((void**)&fusedp, g_fused);
    cudaGetSymbolAddress((void**)&xwp, g_xw);
    cudaGetSymbolAddress((void**)&h1p, g_h1);

    // --- CSR build (independent; issue first) ---
    deg_init_kernel<<<(N_NODES + 255) / 256, 256>>>();
    deg_count_kernel<<<(N_EDGESC + 255) / 256, 256>>>(dst);
    exscan_kernel<<<1, 1024>>>();
    cursor_copy_kernel<<<(N_NODES + 255) / 256, 256>>>();
    fill_edges_kernel<<<(N_EDGESC + 255) / 256, 256>>>(src, dst);
    fill_self_kernel<<<(N_NODES + 255) / 256, 256>>>();

    // --- cross attention ---
    {
        dim3 grid((FEAT + 63) / 64, (N_PAIRS + 127) / 128, 3);
        qkv_kernel<<<grid, 256>>>(f_sub, f_com, Wq, bq, Wk, bk, Wv, bv, qp, kp, vp);
    }
    {
        dim3 grid(N_PAIRS / 64, N_PAIRS / 128);
        sgemm_kernel<true><<<grid, 256>>>(qp, kp, nullptr, nullptr, Sp,
                                          N_PAIRS, N_PAIRS, FEAT);
    }
    softmax4096<<<N_PAIRS, 256>>>(Sp);
    {
        dim3 grid((FEAT + 63) / 64, N_PAIRS / 128, KSPLIT);
        sgemm_splitk_kernel<<<grid, 256>>>(Sp, vp, partp, N_PAIRS, FEAT, N_PAIRS,
                                           N_PAIRS / KSPLIT);
        int n4 = N_PAIRS * FEAT / 4;
        splitk_reduce_kernel<<<(n4 + 255) / 256, 256>>>(
            (const float4*)partp, (const float4*)f_sub, (float4*)attnp,
            n4, (size_t)N_PAIRS * FEAT / 4);
    }
    {
        dim3 grid((FEAT + 63) / 64, N_PAIRS / 128);
        sgemm_kernel<false><<<grid, 256>>>(attnp, Wf, bf, nullptr, fusedp,
                                           N_PAIRS, FEAT, FEAT);
    }

    // --- scatter fused rows into node features (last-index-wins) ---
    copy_x_kernel<<<(N_NODES * FEAT / 4 + 255) / 256, 256>>>((const float4*)x);
    winner_init_kernel<<<(N_NODES + 255) / 256, 256>>>();
    winner_max_kernel<<<(N_PAIRS + 255) / 256, 256>>>(com_ix);
    scatter_fused_kernel<<<(N_PAIRS * FEAT + 255) / 256, 256>>>(com_ix);

    // --- GAT layer 1 ---
    {
        dim3 grid((H1DIM + 63) / 64, (N_NODES + 127) / 128);
        sgemm_kernel<false><<<grid, 256>>>(xwp, W1, nullptr, nullptr, h1p,
                                           N_NODES, H1DIM, FEAT);
    }
    e1_kernel<<<(N_NODES * HEADS + 7) / 8, 256>>>(as1, ad1);
    gat_agg1_kernel<<<(N_NODES + 7) / 8, 256>>>(b1);

    // --- GAT layer 2 ---
    w2e2_kernel<<<(N_NODES + 7) / 8, 256>>>(W2, as2, ad2);
    gat_agg2_kernel<<<(N_NODES + 7) / 8, 256>>>(b2);

    // --- pair scores ---
    score_kernel<<<(N_SP + 255) / 256, 256>>>(pair, out);
}

// round 16
// speedup vs baseline: 1.0618x; 1.0618x over previous
#include <cuda_runtime.h>
#include <math.h>

#define N_NODES 50000
#define N_PAIRS 4096
#define N_EDGESC 500000
#define N_SP    1000000
#define FEAT 300
#define HID 128
#define HEADS 3
#define H1DIM 384
#define OUTC 10
#define ETOT (N_EDGESC + N_NODES)
#define KSPLIT 4

// ------------------- scratch (device globals; no allocation) -------------------
__device__ float g_q[N_PAIRS * FEAT];
__device__ float g_k[N_PAIRS * FEAT];
__device__ float g_v[N_PAIRS * FEAT];
__device__ float g_S[(size_t)N_PAIRS * N_PAIRS];
__device__ float g_part[(size_t)KSPLIT * N_PAIRS * FEAT];
__device__ float g_attn[N_PAIRS * FEAT];
__device__ float g_fused[N_PAIRS * FEAT];
__device__ float g_xw[(size_t)N_NODES * FEAT];
__device__ float g_h1[(size_t)N_NODES * H1DIM];
__device__ float g_out1[(size_t)N_NODES * H1DIM];
__device__ float g_h2[N_NODES * OUTC];
__device__ float g_emb[N_NODES * OUTC];
__device__ float g_es1[N_NODES * HEADS];
__device__ float g_ed1[N_NODES * HEADS];
__device__ float g_es2[N_NODES];
__device__ float g_ed2[N_NODES];
__device__ int   g_deg[N_NODES];
__device__ int   g_rowptr[N_NODES + 1];
__device__ int   g_cursor[N_NODES];
__device__ int   g_adj[ETOT];
__device__ int   g_winner[N_NODES];

__device__ __forceinline__ float lrelu(float x) { return x > 0.f ? x : 0.2f * x; }

// ------------------- SGEMM core: 64x64 tile, 4x4 microtile, BK=16 ------------
// Register double-buffered: prefetch tile t+1 to regs while computing tile t.
// A: [M,K] row-major. TB=false: B [K,N]. TB=true: B [N,K] (C = A @ B^T).
template <bool TB>
__device__ __forceinline__ void gemm_body(
    const float* __restrict__ A, const float* __restrict__ B,
    const float* __restrict__ bias, const float* __restrict__ addm,
    float* __restrict__ C, int M, int N, int K, int kbeg, int kend)
{
    __shared__ __align__(16) float As[16][68];
    __shared__ __align__(16) float Bs[16][68];
    int bm = blockIdx.y * 64, bn = blockIdx.x * 64;
    int tid = threadIdx.x;
    int tx = tid & 15, ty = tid >> 4;
    float acc[4][4] = {};
    float pa[4], pb[4];

    // ---- prologue: load first tile to regs, store to smem ----
#pragma unroll
    for (int i = 0; i < 4; i++) {
        int idx = tid + 256 * i;
        int m = idx >> 4, kk = idx & 15;
        int gm = bm + m, gk = kbeg + kk;
        pa[i] = (gm < M && gk < kend) ? A[(size_t)gm * K + gk] : 0.f;
    }
    if (!TB) {
#pragma unroll
        for (int i = 0; i < 4; i++) {
            int idx = tid + 256 * i;
            int kk = idx >> 6, nn = idx & 63;
            int gk = kbeg + kk, gn = bn + nn;
            pb[i] = (gk < kend && gn < N) ? B[(size_t)gk * N + gn] : 0.f;
        }
    } else {
#pragma unroll
        for (int i = 0; i < 4; i++) {
            int idx = tid + 256 * i;
            int nn = idx >> 4, kk = idx & 15;
            int gn = bn + nn, gk = kbeg + kk;
            pb[i] = (gn < N && gk < kend) ? B[(size_t)gn * K + gk] : 0.f;
        }
    }
#pragma unroll
    for (int i = 0; i < 4; i++) {
        int idx = tid + 256 * i;
        As[idx & 15][idx >> 4] = pa[i];
    }
    if (!TB) {
#pragma unroll
        for (int i = 0; i < 4; i++) {
            int idx = tid + 256 * i;
            Bs[idx >> 6][idx & 63] = pb[i];
        }
    } else {
#pragma unroll
        for (int i = 0; i < 4; i++) {
            int idx = tid + 256 * i;
            Bs[idx & 15][idx >> 4] = pb[i];
        }
    }

    for (int k0 = kbeg; k0 < kend; k0 += 16) {
        __syncthreads();   // smem tile ready
        const bool more = (k0 + 16 < kend);
        if (more) {
            // ---- prefetch next tile to regs (overlaps compute below) ----
            int k1 = k0 + 16;
#pragma unroll
            for (int i = 0; i < 4; i++) {
                int idx = tid + 256 * i;
                int m = idx >> 4, kk = idx & 15;
                int gm = bm + m, gk = k1 + kk;
                pa[i] = (gm < M && gk < kend) ? A[(size_t)gm * K + gk] : 0.f;
            }
            if (!TB) {
#pragma unroll
                for (int i = 0; i < 4; i++) {
                    int idx = tid + 256 * i;
                    int kk = idx >> 6, nn = idx & 63;
                    int gk = k1 + kk, gn = bn + nn;
                    pb[i] = (gk < kend && gn < N) ? B[(size_t)gk * N + gn] : 0.f;
                }
            } else {
#pragma unroll
                for (int i = 0; i < 4; i++) {
                    int idx = tid + 256 * i;
                    int nn = idx >> 4, kk = idx & 15;
                    int gn = bn + nn, gk = k1 + kk;
                    pb[i] = (gn < N && gk < kend) ? B[(size_t)gn * K + gk] : 0.f;
                }
            }
        }
        // ---- compute current tile from smem ----
#pragma unroll
        for (int kk = 0; kk < 16; kk++) {
            float4 av = *reinterpret_cast<const float4*>(&As[kk][ty * 4]);
            float4 bv = *reinterpret_cast<const float4*>(&Bs[kk][tx * 4]);
            float a[4] = {av.x, av.y, av.z, av.w};
            float b[4] = {bv.x, bv.y, bv.z, bv.w};
#pragma unroll
            for (int i = 0; i < 4; i++)
#pragma unroll
                for (int j = 0; j < 4; j++)
                    acc[i][j] += a[i] * b[j];
        }
        __syncthreads();   // everyone done reading smem
        if (more) {
            // ---- store prefetched regs to smem ----
#pragma unroll
            for (int i = 0; i < 4; i++) {
                int idx = tid + 256 * i;
                As[idx & 15][idx >> 4] = pa[i];
            }
            if (!TB) {
#pragma unroll
                for (int i = 0; i < 4; i++) {
                    int idx = tid + 256 * i;
                    Bs[idx >> 6][idx & 63] = pb[i];
                }
            } else {
#pragma unroll
                for (int i = 0; i < 4; i++) {
                    int idx = tid + 256 * i;
                    Bs[idx & 15][idx >> 4] = pb[i];
                }
            }
        }
    }
#pragma unroll
    for (int i = 0; i < 4; i++) {
        int gm = bm + ty * 4 + i;
        if (gm >= M) continue;
#pragma unroll
        for (int j = 0; j < 4; j++) {
            int gn = bn + tx * 4 + j;
            if (gn >= N) continue;
            float vv = acc[i][j];
            if (bias) vv += bias[gn];
            if (addm) vv += addm[(size_t)gm * N + gn];
            C[(size_t)gm * N + gn] = vv;
        }
    }
}

template <bool TB>
__global__ void sgemm_kernel(const float* __restrict__ A, const float* __restrict__ B,
                             const float* __restrict__ bias, const float* __restrict__ addm,
                             float* __restrict__ C, int M, int N, int K)
{
    gemm_body<TB>(A, B, bias, addm, C, M, N, K, 0, K);
}

// split-K: grid.z slices of K, partials into Cpart[z][M*N]
__global__ void sgemm_splitk_kernel(const float* __restrict__ A, const float* __restrict__ B,
                                    float* __restrict__ Cpart, int M, int N, int K, int klen)
{
    int kbeg = blockIdx.z * klen;
    int kend = kbeg + klen < K ? kbeg + klen : K;
    gemm_body<false>(A, B, nullptr, nullptr,
                     Cpart + (size_t)blockIdx.z * M * N, M, N, K, kbeg, kend);
}

__global__ void splitk_reduce_kernel(const float4* __restrict__ part,
                                     const float4* __restrict__ addm,
                                     float4* __restrict__ C, int n4, size_t stride4)
{
    int i = blockIdx.x * blockDim.x + threadIdx.x;
    if (i >= n4) return;
    float4 s = addm[i];
#pragma unroll
    for (int z = 0; z < KSPLIT; z++) {
        float4 p = part[(size_t)z * stride4 + i];
        s.x += p.x; s.y += p.y; s.z += p.z; s.w += p.w;
    }
    C[i] = s;
}

// batched q/k/v projection: grid.z picks (A,B,bias,C)
__global__ void qkv_kernel(const float* __restrict__ fs, const float* __restrict__ fc,
                           const float* __restrict__ Wq, const float* __restrict__ bq,
                           const float* __restrict__ Wk, const float* __restrict__ bk,
                           const float* __restrict__ Wv, const float* __restrict__ bv,
                           float* __restrict__ q, float* __restrict__ k, float* __restrict__ v)
{
    const float* A; const float* B; const float* bias; float* C;
    if (blockIdx.z == 0)      { A = fs; B = Wq; bias = bq; C = q; }
    else if (blockIdx.z == 1) { A = fc; B = Wk; bias = bk; C = k; }
    else                      { A = fc; B = Wv; bias = bv; C = v; }
    gemm_body<false>(A, B, bias, nullptr, C, N_PAIRS, FEAT, FEAT, 0, FEAT);
}

// ------------------- row softmax of the 4096x4096 score matrix ---------------
__global__ void softmax4096(float* __restrict__ S)
{
    int row = blockIdx.x;
    float4* r = reinterpret_cast<float4*>(S + (size_t)row * 4096);
    const float scale = 0.05773502691896258f; // 1/sqrt(300)
    float4 vals[4];
    float mx = -1e30f;
#pragma unroll
    for (int i = 0; i < 4; i++) {
        float4 v = r[threadIdx.x + 256 * i];
        v.x *= scale; v.y *= scale; v.z *= scale; v.w *= scale;
        vals[i] = v;
        mx = fmaxf(mx, fmaxf(fmaxf(v.x, v.y), fmaxf(v.z, v.w)));
    }
    __shared__ float sh[8];
    for (int o = 16; o; o >>= 1) mx = fmaxf(mx, __shfl_xor_sync(0xffffffffu, mx, o));
    int w = threadIdx.x >> 5;
    if ((threadIdx.x & 31) == 0) sh[w] = mx;
    __syncthreads();
    mx = sh[0];
#pragma unroll
    for (int i = 1; i < 8; i++) mx = fmaxf(mx, sh[i]);
    __syncthreads();
    float se = 0.f;
#pragma unroll
    for (int i = 0; i < 4; i++) {
        vals[i].x = __expf(vals[i].x - mx); vals[i].y = __expf(vals[i].y - mx);
        vals[i].z = __expf(vals[i].z - mx); vals[i].w = __expf(vals[i].w - mx);
        se += vals[i].x + vals[i].y + vals[i].z + vals[i].w;
    }
    for (int o = 16; o; o >>= 1) se += __shfl_xor_sync(0xffffffffu, se, o);
    if ((threadIdx.x & 31) == 0) sh[w] = se;
    __syncthreads();
    se = 0.f;
#pragma unroll
    for (int i = 0; i < 8; i++) se += sh[i];
    float inv = 1.f / se;
#pragma unroll
    for (int i = 0; i < 4; i++) {
        vals[i].x *= inv; vals[i].y *= inv; vals[i].z *= inv; vals[i].w *= inv;
        r[threadIdx.x + 256 * i] = vals[i];
    }
}

// ------------------- x_work = x; scatter fused rows (last-index-wins) --------
__global__ void copy_x_kernel(const float4* __restrict__ x)
{
    size_t t = (size_t)blockIdx.x * blockDim.x + threadIdx.x;
    if (t < (size_t)N_NODES * FEAT / 4) reinterpret_cast<float4*>(g_xw)[t] = x[t];
}

__global__ void winner_init_kernel()
{
    int n = blockIdx.x * blockDim.x + threadIdx.x;
    if (n < N_NODES) g_winner[n] = -1;
}

__global__ void winner_max_kernel(const int* __restrict__ cidx)
{
    int i = blockIdx.x * blockDim.x + threadIdx.x;
    if (i < N_PAIRS) atomicMax(&g_winner[cidx[i]], i);
}

__global__ void scatter_fused_kernel(const int* __restrict__ cidx)
{
    int t = blockIdx.x * blockDim.x + threadIdx.x;
    if (t < N_PAIRS * FEAT) {
        int i = t / FEAT, c = t - i * FEAT;
        int node = cidx[i];
        if (g_winner[node] == i) g_xw[(size_t)node * FEAT + c] = g_fused[t];
    }
}

// ------------------- CSR build (by dst, includes self-loops) -----------------
__global__ void deg_init_kernel()
{
    int n = blockIdx.x * blockDim.x + threadIdx.x;
    if (n < N_NODES) g_deg[n] = 1;  // self-loop
}

__global__ void deg_count_kernel(const int* __restrict__ dst)
{
    int e = blockIdx.x * blockDim.x + threadIdx.x;
    if (e < N_EDGESC) atomicAdd(&g_deg[dst[e]], 1);
}

__global__ void exscan_kernel()
{
    __shared__ int wsum[32];
    __shared__ int carry;
    if (threadIdx.x == 0) carry = 0;
    int lane = threadIdx.x & 31, wid = threadIdx.x >> 5;
    __syncthreads();
    for (int base = 0; base < N_NODES; base += 1024) {
        int i = base + threadIdx.x;
        int v = (i < N_NODES) ? g_deg[i] : 0;
        int x = v;
        for (int o = 1; o < 32; o <<= 1) {
            int t = __shfl_up_sync(0xffffffffu, x, o);
            if (lane >= o) x += t;
        }
        if (lane == 31) wsum[wid] = x;
        __syncthreads();
        if (wid == 0) {
            int y = wsum[lane];
            for (int o = 1; o < 32; o <<= 1) {
                int t = __shfl_up_sync(0xffffffffu, y, o);
                if (lane >= o) y += t;
            }
            wsum[lane] = y;
        }
        __syncthreads();
        int incl = x + (wid ? wsum[wid - 1] : 0);
        int c = carry;
        if (i < N_NODES) g_rowptr[i + 1] = c + incl;
        __syncthreads();
        if (threadIdx.x == 1023) carry = c + incl;
        __syncthreads();
    }
    if (threadIdx.x == 0) g_rowptr[0] = 0;
}

__global__ void cursor_copy_kernel()
{
    int n = blockIdx.x * blockDim.x + threadIdx.x;
    if (n < N_NODES) g_cursor[n] = g_rowptr[n];
}

__global__ void fill_edges_kernel(const int* __restrict__ src, const int* __restrict__ dst)
{
    int e = blockIdx.x * blockDim.x + threadIdx.x;
    if (e < N_EDGESC) {
        int d = dst[e];
        int p = atomicAdd(&g_cursor[d], 1);
        g_adj[p] = src[e];
    }
}

__global__ void fill_self_kernel()
{
    int n = blockIdx.x * blockDim.x + threadIdx.x;
    if (n < N_NODES) {
        int p = atomicAdd(&g_cursor[n], 1);
        g_adj[p] = n;
    }
}

// ------------------- layer-1 attention coefficients (warp per node-head) -----
__global__ void e1_kernel(const float* __restrict__ asrc, const float* __restrict__ adst)
{
    int g = blockIdx.x * (blockDim.x >> 5) + (threadIdx.x >> 5);
    if (g >= N_NODES * HEADS) return;
    int n = g / 3, h = g - n * 3;
    int lane = threadIdx.x & 31;
    const float4* row = reinterpret_cast<const float4*>(g_h1 + (size_t)n * H1DIM + h * HID);
    const float4* as4 = reinterpret_cast<const float4*>(asrc + h * HID);
    const float4* ad4 = reinterpret_cast<const float4*>(adst + h * HID);
    float4 hv = row[lane], av = as4[lane], dv = ad4[lane];
    float s = hv.x * av.x + hv.y * av.y + hv.z * av.z + hv.w * av.w;
    float d = hv.x * dv.x + hv.y * dv.y + hv.z * dv.z + hv.w * dv.w;
    for (int o = 16; o; o >>= 1) {
        s += __shfl_xor_sync(0xffffffffu, s, o);
        d += __shfl_xor_sync(0xffffffffu, d, o);
    }
    if (lane == 0) {
        g_es1[n * HEADS + h] = s;
        g_ed1[n * HEADS + h] = d;
    }
}

// ------------------- GAT layer-1 aggregation (warp per node) + bias + ELU ----
__global__ void gat_agg1_kernel(const float* __restrict__ b1)
{
    int n = blockIdx.x * (blockDim.x >> 5) + (threadIdx.x >> 5);
    int lane = threadIdx.x & 31;
    if (n >= N_NODES) return;
    int s = g_rowptr[n], e = g_rowptr[n + 1];
    float ed0 = g_ed1[n * 3 + 0], ed1 = g_ed1[n * 3 + 1], ed2 = g_ed1[n * 3 + 2];

    float m0 = -1e30f, m1 = -1e30f, m2 = -1e30f;
    for (int j = s + lane; j < e; j += 32) {
        int sj = g_adj[j];
        m0 = fmaxf(m0, lrelu(g_es1[sj * 3 + 0] + ed0));
        m1 = fmaxf(m1, lrelu(g_es1[sj * 3 + 1] + ed1));
        m2 = fmaxf(m2, lrelu(g_es1[sj * 3 + 2] + ed2));
    }
    for (int o = 16; o; o >>= 1) {
        m0 = fmaxf(m0, __shfl_xor_sync(0xffffffffu, m0, o));
        m1 = fmaxf(m1, __shfl_xor_sync(0xffffffffu, m1, o));
        m2 = fmaxf(m2, __shfl_xor_sync(0xffffffffu, m2, o));
    }
    float d0 = 0.f, d1 = 0.f, d2 = 0.f;
    for (int j = s + lane; j < e; j += 32) {
        int sj = g_adj[j];
        d0 += __expf(lrelu(g_es1[sj * 3 + 0] + ed0) - m0);
        d1 += __expf(lrelu(g_es1[sj * 3 + 1] + ed1) - m1);
        d2 += __expf(lrelu(g_es1[sj * 3 + 2] + ed2) - m2);
    }
    for (int o = 16; o; o >>= 1) {
        d0 += __shfl_xor_sync(0xffffffffu, d0, o);
        d1 += __shfl_xor_sync(0xffffffffu, d1, o);
        d2 += __shfl_xor_sync(0xffffffffu, d2, o);
    }
    float inv0 = 1.f / (d0 + 1e-16f), inv1 = 1.f / (d1 + 1e-16f), inv2 = 1.f / (d2 + 1e-16f);

    // chunked accumulation: each lane computes alpha for ONE edge, broadcast
    float4 acc0 = {0, 0, 0, 0}, acc1 = {0, 0, 0, 0}, acc2 = {0, 0, 0, 0};
    for (int base = s; base < e; base += 32) {
        int j = base + lane;
        int sj = 0;
        float w0 = 0.f, w1 = 0.f, w2 = 0.f;
        if (j < e) {
            sj = g_adj[j];
            w0 = __expf(lrelu(g_es1[sj * 3 + 0] + ed0) - m0) * inv0;
            w1 = __expf(lrelu(g_es1[sj * 3 + 1] + ed1) - m1) * inv1;
            w2 = __expf(lrelu(g_es1[sj * 3 + 2] + ed2) - m2) * inv2;
        }
        int cnt = e - base; if (cnt > 32) cnt = 32;
        for (int t = 0; t < cnt; t++) {
            int   sjt = __shfl_sync(0xffffffffu, sj, t);
            float u0  = __shfl_sync(0xffffffffu, w0, t);
            float u1  = __shfl_sync(0xffffffffu, w1, t);
            float u2  = __shfl_sync(0xffffffffu, w2, t);
            const float4* row = reinterpret_cast<const float4*>(g_h1 + (size_t)sjt * H1DIM);
            float4 r0 = row[lane], r1 = row[lane + 32], r2 = row[lane + 64];
            acc0.x += u0 * r0.x; acc0.y += u0 * r0.y; acc0.z += u0 * r0.z; acc0.w += u0 * r0.w;
            acc1.x += u1 * r1.x; acc1.y += u1 * r1.y; acc1.z += u1 * r1.z; acc1.w += u1 * r1.w;
            acc2.x += u2 * r2.x; acc2.y += u2 * r2.y; acc2.z += u2 * r2.z; acc2.w += u2 * r2.w;
        }
    }
    // bias + ELU, vectorized store
    float* o = g_out1 + (size_t)n * H1DIM;
    const float4* bv = reinterpret_cast<const float4*>(b1);
    float4 outv;
    float4 bb = bv[lane];
    outv.x = acc0.x + bb.x; outv.y = acc0.y + bb.y; outv.z = acc0.z + bb.z; outv.w = acc0.w + bb.w;
    outv.x = outv.x > 0.f ? outv.x : expm1f(outv.x);
    outv.y = outv.y > 0.f ? outv.y : expm1f(outv.y);
    outv.z = outv.z > 0.f ? outv.z : expm1f(outv.z);
    outv.w = outv.w > 0.f ? outv.w : expm1f(outv.w);
    reinterpret_cast<float4*>(o)[lane] = outv;
    bb = bv[lane + 32];
    outv.x = acc1.x + bb.x; outv.y = acc1.y + bb.y; outv.z = acc1.z + bb.z; outv.w = acc1.w + bb.w;
    outv.x = outv.x > 0.f ? outv.x : expm1f(outv.x);
    outv.y = outv.y > 0.f ? outv.y : expm1f(outv.y);
    outv.z = outv.z > 0.f ? outv.z : expm1f(outv.z);
    outv.w = outv.w > 0.f ? outv.w : expm1f(outv.w);
    reinterpret_cast<float4*>(o)[lane + 32] = outv;
    bb = bv[lane + 64];
    outv.x = acc2.x + bb.x; outv.y = acc2.y + bb.y; outv.z = acc2.z + bb.z; outv.w = acc2.w + bb.w;
    outv.x = outv.x > 0.f ? outv.x : expm1f(outv.x);
    outv.y = outv.y > 0.f ? outv.y : expm1f(outv.y);
    outv.z = outv.z > 0.f ? outv.z : expm1f(outv.z);
    outv.w = outv.w > 0.f ? outv.w : expm1f(outv.w);
    reinterpret_cast<float4*>(o)[lane + 64] = outv;
}

// ------------------- h2 = out1 @ W2 (N=10) + e2 coefficients, warp per row ---
__global__ void w2e2_kernel(const float* __restrict__ W2,
                            const float* __restrict__ as2, const float* __restrict__ ad2)
{
    __shared__ float wT[OUTC * H1DIM];  // transposed: wT[c*384+k]
    for (int idx = threadIdx.x; idx < H1DIM * OUTC; idx += blockDim.x) {
        int k = idx / OUTC, c = idx - k * OUTC;
        wT[c * H1DIM + k] = W2[idx];
    }
    __syncthreads();
    int warp = threadIdx.x >> 5, lane = threadIdx.x & 31;
    int row = blockIdx.x * 8 + warp;
    if (row >= N_NODES) return;
    float acc[OUTC] = {};
    const float* xr = g_out1 + (size_t)row * H1DIM;
    for (int k = lane; k < H1DIM; k += 32) {
        float xv = xr[k];
#pragma unroll
        for (int c = 0; c < OUTC; c++) acc[c] += xv * wT[c * H1DIM + k];
    }
#pragma unroll
    for (int c = 0; c < OUTC; c++)
        for (int o = 16; o; o >>= 1) acc[c] += __shfl_xor_sync(0xffffffffu, acc[c], o);
    if (lane == 0) {
        float s = 0.f, d = 0.f;
#pragma unroll
        for (int c = 0; c < OUTC; c++) {
            g_h2[(size_t)row * OUTC + c] = acc[c];  // no bias before attention
            s += acc[c] * as2[c];
            d += acc[c] * ad2[c];
        }
        g_es2[row] = s;
        g_ed2[row] = d;
    }
}

// ------------------- GAT layer-2 aggregation (warp per node) + bias ----------
__global__ void gat_agg2_kernel(const float* __restrict__ b2)
{
    int n = blockIdx.x * (blockDim.x >> 5) + (threadIdx.x >> 5);
    int lane = threadIdx.x & 31;
    if (n >= N_NODES) return;
    int s = g_rowptr[n], e = g_rowptr[n + 1];
    float ed = g_ed2[n];

    float m = -1e30f;
    for (int j = s + lane; j < e; j += 32) m = fmaxf(m, lrelu(g_es2[g_adj[j]] + ed));
    for (int o = 16; o; o >>= 1) m = fmaxf(m, __shfl_xor_sync(0xffffffffu, m, o));
    float den = 0.f;
    for (int j = s + lane; j < e; j += 32) den += __expf(lrelu(g_es2[g_adj[j]] + ed) - m);
    for (int o = 16; o; o >>= 1) den += __shfl_xor_sync(0xffffffffu, den, o);
    float inv = 1.f / (den + 1e-16f);

    float acc[OUTC] = {};
    for (int j = s + lane; j < e; j += 32) {
        int sj = g_adj[j];
        float al = __expf(lrelu(g_es2[sj] + ed) - m) * inv;
        const float* r = g_h2 + (size_t)sj * OUTC;
#pragma unroll
        for (int c = 0; c < OUTC; c++) acc[c] += al * r[c];
    }
#pragma unroll
    for (int c = 0; c < OUTC; c++)
        for (int o = 16; o; o >>= 1) acc[c] += __shfl_xor_sync(0xffffffffu, acc[c], o);
    if (lane == 0) {
#pragma unroll
        for (int c = 0; c < OUTC; c++) g_emb[(size_t)n * OUTC + c] = acc[c] + b2[c];
    }
}

// ------------------- pair scoring --------------------------------------------
__global__ void score_kernel(const int* __restrict__ pair, float* __restrict__ out)
{
    int p = blockIdx.x * blockDim.x + threadIdx.x;
    if (p >= N_SP) return;
    const float* a = g_emb + (size_t)pair[2 * p] * OUTC;
    const float* b = g_emb + (size_t)pair[2 * p + 1] * OUTC;
    float s = 0.f;
#pragma unroll
    for (int c = 0; c < OUTC; c++) s += a[c] * b[c];
    out[p] = s;
}

// ------------------- host orchestration --------------------------------------
extern "C" void kernel_launch(void* const* d_in, const int* in_sizes, int n_in,
                              void* d_out, int out_size)
{
    const float* f_sub  = (const float*)d_in[0];
    const float* f_com  = (const float*)d_in[1];
    const float* x      = (const float*)d_in[2];
    const int*   com_ix = (const int*)d_in[3];
    const int*   eidx   = (const int*)d_in[4];
    const int*   pair   = (const int*)d_in[5];
    const float* Wq = (const float*)d_in[6],  *bq = (const float*)d_in[7];
    const float* Wk = (const float*)d_in[8],  *bk = (const float*)d_in[9];
    const float* Wv = (const float*)d_in[10], *bv = (const float*)d_in[11];
    const float* Wf = (const float*)d_in[12], *bf = (const float*)d_in[13];
    const float* W1 = (const float*)d_in[14];
    const float* as1 = (const float*)d_in[15], *ad1 = (const float*)d_in[16];
    const float* b1 = (const float*)d_in[17];
    const float* W2 = (const float*)d_in[18];
    const float* as2 = (const float*)d_in[19], *ad2 = (const float*)d_in[20];
    const float* b2 = (const float*)d_in[21];
    float* out = (float*)d_out;

    const int* src = eidx;
    const int* dst = eidx + N_EDGESC;

    float *qp, *kp, *vp, *Sp, *partp, *attnp, *fusedp, *xwp, *h1p;
    cudaGetSymbolAddress((void**)&qp, g_q);
    cudaGetSymbolAddress((void**)&kp, g_k);
    cudaGetSymbolAddress((void**)&vp, g_v);
    cudaGetSymbolAddress((void**)&Sp, g_S);
    cudaGetSymbolAddress((void**)&partp, g_part);
    cudaGetSymbolAddress((void**)&attnp, g_attn);
    cudaGetSymbolAddress((void**)&fusedp, g_fused);
    cudaGetSymbolAddress((void**)&xwp, g_xw);
    cudaGetSymbolAddress((void**)&h1p, g_h1);

    // --- CSR build (independent; issue first) ---
    deg_init_kernel<<<(N_NODES + 255) / 256, 256>>>();
    deg_count_kernel<<<(N_EDGESC + 255) / 256, 256>>>(dst);
    exscan_kernel<<<1, 1024>>>();
    cursor_copy_kernel<<<(N_NODES + 255) / 256, 256>>>();
    fill_edges_kernel<<<(N_EDGESC + 255) / 256, 256>>>(src, dst);
    fill_self_kernel<<<(N_NODES + 255) / 256, 256>>>();

    // --- cross attention ---
    {
        dim3 grid((FEAT + 63) / 64, N_PAIRS / 64, 3);
        qkv_kernel<<<grid, 256>>>(f_sub, f_com, Wq, bq, Wk, bk, Wv, bv, qp, kp, vp);
    }
    {
        dim3 grid(N_PAIRS / 64, N_PAIRS / 64);
        sgemm_kernel<true><<<grid, 256>>>(qp, kp, nullptr, nullptr, Sp,
                                          N_PAIRS, N_PAIRS, FEAT);
    }
    softmax4096<<<N_PAIRS, 256>>>(Sp);
    {
        dim3 grid((FEAT + 63) / 64, N_PAIRS / 64, KSPLIT);
        sgemm_splitk_kernel<<<grid, 256>>>(Sp, vp, partp, N_PAIRS, FEAT, N_PAIRS,
                                           N_PAIRS / KSPLIT);
        int n4 = N_PAIRS * FEAT / 4;
        splitk_reduce_kernel<<<(n4 + 255) / 256, 256>>>(
            (const float4*)partp, (const float4*)f_sub, (float4*)attnp,
            n4, (size_t)N_PAIRS * FEAT / 4);
    }
    {
        dim3 grid((FEAT + 63) / 64, N_PAIRS / 64);
        sgemm_kernel<false><<<grid, 256>>>(attnp, Wf, bf, nullptr, fusedp,
                                           N_PAIRS, FEAT, FEAT);
    }

    // --- scatter fused rows into node features (last-index-wins) ---
    copy_x_kernel<<<(N_NODES * FEAT / 4 + 255) / 256, 256>>>((const float4*)x);
    winner_init_kernel<<<(N_NODES + 255) / 256, 256>>>();
    winner_max_kernel<<<(N_PAIRS + 255) / 256, 256>>>(com_ix);
    scatter_fused_kernel<<<(N_PAIRS * FEAT + 255) / 256, 256>>>(com_ix);

    // --- GAT layer 1 ---
    {
        dim3 grid((H1DIM + 63) / 64, (N_NODES + 63) / 64);
        sgemm_kernel<false><<<grid, 256>>>(xwp, W1, nullptr, nullptr, h1p,
                                           N_NODES, H1DIM, FEAT);
    }
    e1_kernel<<<(N_NODES * HEADS + 7) / 8, 256>>>(as1, ad1);
    gat_agg1_kernel<<<(N_NODES + 7) / 8, 256>>>(b1);

    // --- GAT layer 2 ---
    w2e2_kernel<<<(N_NODES + 7) / 8, 256>>>(W2, as2, ad2);
    gat_agg2_kernel<<<(N_NODES + 7) / 8, 256>>>(b2);

    // --- pair scores ---
    score_kernel<<<(N_SP + 255) / 256, 256>>>(pair, out);
}